// round 8
// baseline (speedup 1.0000x reference)
#include <cuda_runtime.h>
#include <math.h>

#define B   16
#define Hh  128
#define Ww  128
#define CI  64
#define CO  64
#define MD  16
#define THETA 0.04908738521234052f   // 2*pi/128

typedef unsigned long long u64;

__device__ __forceinline__ u64 pk(float lo, float hi) {
    u64 r; asm("mov.b64 %0, {%1,%2};" : "=l"(r) : "f"(lo), "f"(hi)); return r;
}
__device__ __forceinline__ u64 fma2(u64 a, u64 b, u64 c) {
    u64 d; asm("fma.rn.f32x2 %0, %1, %2, %3;" : "=l"(d) : "l"(a), "l"(b), "l"(c)); return d;
}
__device__ __forceinline__ u64 add2(u64 a, u64 b) {
    u64 d; asm("add.rn.f32x2 %0, %1, %2;" : "=l"(d) : "l"(a), "l"(b)); return d;
}
#define SGN2 0x8000000080000000ULL

// ---- scratch (device globals; allocation-free). 16B aligned ----
static __device__ __align__(16) float g_Ax[B*MD*Hh*CI];     // [b][kx][h][i]  8 MB
static __device__ __align__(16) float g_Ay[B*MD*Hh*CI];     //                8 MB
static __device__ __align__(16) float g_Xx[MD*MD*B*CI];     // [m][b][i]      1 MB
static __device__ __align__(16) float g_Xy[MD*MD*B*CI];     //                1 MB
static __device__ __align__(16) float g_Wr[MD*MD*CI*CO];    // [m][i*64+o]    4 MB
static __device__ __align__(16) float g_Wi[MD*MD*CI*CO];    //                4 MB
static __device__ __align__(16) float g_Ox[B*MD*MD*CO];     // [b][kx][ky][o] 1 MB
static __device__ __align__(16) float g_Oy[B*MD*MD*CO];     //                1 MB
static __device__ __align__(16) float g_Gx[B*Hh*MD*CO];     // [b][h][kx][o]  8 MB
static __device__ __align__(16) float g_Gy[B*Hh*MD*CO];     //                8 MB

// ============ fused stage A + weight transpose ============
__global__ void __launch_bounds__(128) fusedAT(const float* __restrict__ x,
                                               const float* __restrict__ wr,
                                               const float* __restrict__ wi) {
    __shared__ __align__(16) float pool[4 * 32 * 64];   // 32 KB
    __shared__ __align__(16) u64 sbc[128];
    __shared__ __align__(16) u64 sbs[128];
    int tid = threadIdx.x;

    if (blockIdx.x >= 512) {
        // ---- weight transpose tile: 32 m x 32 io ----
        int t   = blockIdx.x - 512;
        int bm  = t & 7;
        int bio = t >> 3;
        int tx  = tid & 31;
        int ty  = tid >> 5;
        #define SR(a_, b_) pool[(a_) * 33 + (b_)]
        #define SI(a_, b_) pool[1056 + (a_) * 33 + (b_)]
#pragma unroll
        for (int r = 0; r < 8; ++r) {
            int iol = ty + r * 4;
            size_t g = (size_t)(bio * 32 + iol) * 256 + bm * 32 + tx;
            SR(iol, tx) = wr[g];
            SI(iol, tx) = wi[g];
        }
        __syncthreads();
#pragma unroll
        for (int r = 0; r < 8; ++r) {
            int ml = ty + r * 4;
            size_t dst = (size_t)(bm * 32 + ml) * 4096 + bio * 32 + tx;
            g_Wr[dst] = SR(tx, ml);
            g_Wi[dst] = SI(tx, ml);
        }
        return;
    }

    // ---- stage A ----
    {
        float s, c;
        sincosf((float)tid * THETA, &s, &c);
        sbc[tid] = pk(c, c);
        sbs[tid] = pk(s, s);
    }
    int b  = blockIdx.x >> 5;
    int hq = blockIdx.x & 31;
    int h0 = hq * 4;
    int ip = tid & 31, kq = tid >> 5;
    int i0 = 2 * ip;
    int kxs0 = kq, kxs1 = kq + 4, kxs2 = kq + 8, kxs3 = kq + 12;
    u64 re[4][4], im[4][4];
#pragma unroll
    for (int r = 0; r < 4; ++r)
#pragma unroll
        for (int q = 0; q < 4; ++q) { re[r][q] = 0; im[r][q] = 0; }

    for (int wc = 0; wc < 4; ++wc) {
        __syncthreads();
#pragma unroll
        for (int r = 0; r < 4; ++r) {
            const float4* src = (const float4*)(x + ((size_t)(b * Hh + h0 + r) * Ww + wc * 32) * CI);
            float4* dst = (float4*)&pool[r * 2048];
            for (int l = tid; l < 512; l += 128) dst[l] = src[l];
        }
        __syncthreads();
        int w0 = wc * 32;
        int id0 = (kxs0 * w0) & 127, id1 = (kxs1 * w0) & 127;
        int id2 = (kxs2 * w0) & 127, id3 = (kxs3 * w0) & 127;
#pragma unroll 4
        for (int wl = 0; wl < 32; ++wl) {
            u64 v0 = *(const u64*)&pool[0 * 2048 + wl * 64 + i0];
            u64 v1 = *(const u64*)&pool[1 * 2048 + wl * 64 + i0];
            u64 v2 = *(const u64*)&pool[2 * 2048 + wl * 64 + i0];
            u64 v3 = *(const u64*)&pool[3 * 2048 + wl * 64 + i0];
            u64 cc, ss;
            cc = sbc[id0]; ss = sbs[id0]; id0 = (id0 + kxs0) & 127;
            re[0][0]=fma2(v0,cc,re[0][0]); im[0][0]=fma2(v0,ss,im[0][0]);
            re[1][0]=fma2(v1,cc,re[1][0]); im[1][0]=fma2(v1,ss,im[1][0]);
            re[2][0]=fma2(v2,cc,re[2][0]); im[2][0]=fma2(v2,ss,im[2][0]);
            re[3][0]=fma2(v3,cc,re[3][0]); im[3][0]=fma2(v3,ss,im[3][0]);
            cc = sbc[id1]; ss = sbs[id1]; id1 = (id1 + kxs1) & 127;
            re[0][1]=fma2(v0,cc,re[0][1]); im[0][1]=fma2(v0,ss,im[0][1]);
            re[1][1]=fma2(v1,cc,re[1][1]); im[1][1]=fma2(v1,ss,im[1][1]);
            re[2][1]=fma2(v2,cc,re[2][1]); im[2][1]=fma2(v2,ss,im[2][1]);
            re[3][1]=fma2(v3,cc,re[3][1]); im[3][1]=fma2(v3,ss,im[3][1]);
            cc = sbc[id2]; ss = sbs[id2]; id2 = (id2 + kxs2) & 127;
            re[0][2]=fma2(v0,cc,re[0][2]); im[0][2]=fma2(v0,ss,im[0][2]);
            re[1][2]=fma2(v1,cc,re[1][2]); im[1][2]=fma2(v1,ss,im[1][2]);
            re[2][2]=fma2(v2,cc,re[2][2]); im[2][2]=fma2(v2,ss,im[2][2]);
            re[3][2]=fma2(v3,cc,re[3][2]); im[3][2]=fma2(v3,ss,im[3][2]);
            cc = sbc[id3]; ss = sbs[id3]; id3 = (id3 + kxs3) & 127;
            re[0][3]=fma2(v0,cc,re[0][3]); im[0][3]=fma2(v0,ss,im[0][3]);
            re[1][3]=fma2(v1,cc,re[1][3]); im[1][3]=fma2(v1,ss,im[1][3]);
            re[2][3]=fma2(v2,cc,re[2][3]); im[2][3]=fma2(v2,ss,im[2][3]);
            re[3][3]=fma2(v3,cc,re[3][3]); im[3][3]=fma2(v3,ss,im[3][3]);
        }
    }
#pragma unroll
    for (int q = 0; q < 4; ++q) {
        int kx = kq + 4 * q;
#pragma unroll
        for (int r = 0; r < 4; ++r) {
            size_t base = ((size_t)(b * MD + kx) * Hh + (h0 + r)) * CI;
            *(u64*)&g_Ax[base + i0] = re[r][q];
            *(u64*)&g_Ay[base + i0] = im[r][q] ^ SGN2;
        }
    }
}

// ============ stage B: X[m][b][i] = sum_h A e^{-i ky h th} ============
__global__ void __launch_bounds__(256) stageB() {
    __shared__ __align__(16) float sBx[64 * 32];
    __shared__ __align__(16) float sBy[64 * 32];
    __shared__ __align__(16) u64 sbc[128];
    __shared__ __align__(16) u64 sbs[128];
    int b  = blockIdx.x >> 5;
    int kx = (blockIdx.x >> 1) & 15;
    int ic = blockIdx.x & 1;
    int tid = threadIdx.x;
    if (tid < 128) {
        float s, c;
        sincosf((float)tid * THETA, &s, &c);
        sbc[tid] = pk(c, c);
        sbs[tid] = pk(s, s);
    }
    int ipl = tid & 15, ky = tid >> 4;
    int i0 = 2 * ipl;
    u64 P = 0, Q = 0, R = 0, S = 0;
    const float* Abx = g_Ax + (size_t)(b * MD + kx) * Hh * CI;
    const float* Aby = g_Ay + (size_t)(b * MD + kx) * Hh * CI;
    for (int hc = 0; hc < 2; ++hc) {
        __syncthreads();
        for (int l = tid; l < 512; l += 256) {
            int row = l >> 3, q = l & 7;
            int gidx = (hc * 64 + row) * 16 + ic * 8 + q;
            ((float4*)sBx)[l] = ((const float4*)Abx)[gidx];
            ((float4*)sBy)[l] = ((const float4*)Aby)[gidx];
        }
        __syncthreads();
        int idx = (ky * hc * 64) & 127;
#pragma unroll 4
        for (int hl = 0; hl < 64; ++hl) {
            u64 cc = sbc[idx], ss = sbs[idx];
            idx = (idx + ky) & 127;
            u64 ar = *(const u64*)&sBx[hl * 32 + i0];
            u64 ai = *(const u64*)&sBy[hl * 32 + i0];
            P = fma2(ar, cc, P);  Q = fma2(ai, ss, Q);
            R = fma2(ai, cc, R);  S = fma2(ar, ss, S);
        }
    }
    size_t base = ((size_t)(ky * MD + kx) * B + b) * CI + ic * 32;
    *(u64*)&g_Xx[base + i0] = add2(P, Q);
    *(u64*)&g_Xy[base + i0] = add2(R, S ^ SGN2);
}

// ============ stage C v2: O[b][kx][ky][o] = sum_i X[m][b][i]*W[m][i][o] ============
__global__ void __launch_bounds__(256) stageC() {
    __shared__ __align__(16) float sWr[CI * CO];   // 16 KB
    __shared__ __align__(16) float sWi[CI * CO];   // 16 KB
    __shared__ __align__(16) u64 sXx[B * CI];      // 8 KB ( x, x)
    __shared__ __align__(16) u64 sXn[B * CI];      // 8 KB (-y,-y)
    int m = blockIdx.x;
    int kx = m & 15, ky = m >> 4;
    int tid = threadIdx.x;
    const float4* Wr4 = (const float4*)(g_Wr + (size_t)m * 4096);
    const float4* Wi4 = (const float4*)(g_Wi + (size_t)m * 4096);
    for (int l = tid; l < 1024; l += 256) {
        ((float4*)sWr)[l] = Wr4[l];
        ((float4*)sWi)[l] = Wi4[l];
    }
    for (int l = tid; l < 1024; l += 256) {
        float vx = g_Xx[m * 1024 + l];
        float vy = g_Xy[m * 1024 + l];
        sXx[l] = pk(vx, vx);
        sXn[l] = pk(-vy, -vy);
    }
    __syncthreads();
    int oq = tid & 15;    // o = 4*oq .. 4*oq+3 (2 packed pairs)
    int b  = tid >> 4;    // 0..15
    u64 P0=0,P1=0,Q0=0,Q1=0,R0=0,R1=0,S0=0,S1=0;
    const u64* xp = &sXx[b * 64];
    const u64* np = &sXn[b * 64];
#pragma unroll 8
    for (int i = 0; i < CI; ++i) {
        ulonglong2 wr2 = *(const ulonglong2*)&sWr[i * 64 + 4 * oq];
        ulonglong2 wi2 = *(const ulonglong2*)&sWi[i * 64 + 4 * oq];
        u64 xv = xp[i], nv = np[i];
        P0 = fma2(xv, wr2.x, P0);  P1 = fma2(xv, wr2.y, P1);
        Q0 = fma2(nv, wi2.x, Q0);  Q1 = fma2(nv, wi2.y, Q1);
        R0 = fma2(xv, wi2.x, R0);  R1 = fma2(xv, wi2.y, R1);
        S0 = fma2(nv, wr2.x, S0);  S1 = fma2(nv, wr2.y, S1);
    }
    // re = P + Q (Q = sum(-y)*wi) ; im = R - S (S = sum(-y)*wr, so im = R + (-S))
    size_t base = ((size_t)(b * MD + kx) * MD + ky) * CO + 4 * oq;
    *(u64*)&g_Ox[base    ] = add2(P0, Q0);
    *(u64*)&g_Ox[base + 2] = add2(P1, Q1);
    *(u64*)&g_Oy[base    ] = add2(R0, S0 ^ SGN2);
    *(u64*)&g_Oy[base + 2] = add2(R1, S1 ^ SGN2);
}

// ============ stage D v2: G[b][h][kx][o] = sum_ky O e^{+i ky h th} ============
// 1024 blocks (b, kx, h-quarter of 32), 256 thr: thread = (4 o, 2 h)
__global__ void __launch_bounds__(256) stageD() {
    __shared__ __align__(16) float sOx[MD * CO];   // 4 KB
    __shared__ __align__(16) float sOy[MD * CO];   // 4 KB
    __shared__ __align__(16) u64 sTc[MD * 32];     // 4 KB  [ky][hloc]
    __shared__ __align__(16) u64 sTs[MD * 32];     // 4 KB
    int quarter = blockIdx.x & 3;
    int kx      = (blockIdx.x >> 2) & 15;
    int b       = blockIdx.x >> 6;
    int hb      = quarter * 32;
    int tid     = threadIdx.x;
    for (int l = tid; l < 512; l += 256) {
        int ky = l >> 5, hloc = l & 31;
        float s, c;
        sincosf((float)((ky * (hb + hloc)) & 127) * THETA, &s, &c);
        sTc[l] = pk(c, c);
        sTs[l] = pk(s, s);
    }
    const float* Osx = g_Ox + (size_t)(b * MD + kx) * MD * CO;
    const float* Osy = g_Oy + (size_t)(b * MD + kx) * MD * CO;
    for (int l = tid; l < 256; l += 256) {
        ((float4*)sOx)[l] = ((const float4*)Osx)[l];
        ((float4*)sOy)[l] = ((const float4*)Osy)[l];
    }
    __syncthreads();

    int oq = tid & 15;    // o = 4*oq (2 pairs)
    int hg = tid >> 4;    // h = hb + 2*hg + j, j in {0,1}
    u64 re[2][2] = {{0,0},{0,0}};   // [j][pair]
    u64 im[2][2] = {{0,0},{0,0}};
#pragma unroll
    for (int ky = 0; ky < MD; ++ky) {
        ulonglong2 vx = *(const ulonglong2*)&sOx[ky * 64 + 4 * oq];
        ulonglong2 vy = *(const ulonglong2*)&sOy[ky * 64 + 4 * oq];
        u64 vy0n = vx.x; // placeholder to keep reg names clear (overwritten)
        vy0n = vy.x ^ SGN2;
        u64 vy1n = vy.y ^ SGN2;
#pragma unroll
        for (int j = 0; j < 2; ++j) {
            int hl = hg * 2 + j;
            u64 cc = sTc[ky * 32 + hl];
            u64 ss = sTs[ky * 32 + hl];
            // re += vx*cc - vy*ss ; im += vx*ss + vy*cc
            re[j][0] = fma2(vx.x, cc, re[j][0]);  re[j][0] = fma2(vy0n, ss, re[j][0]);
            re[j][1] = fma2(vx.y, cc, re[j][1]);  re[j][1] = fma2(vy1n, ss, re[j][1]);
            im[j][0] = fma2(vx.x, ss, im[j][0]);  im[j][0] = fma2(vy.x, cc, im[j][0]);
            im[j][1] = fma2(vx.y, ss, im[j][1]);  im[j][1] = fma2(vy.y, cc, im[j][1]);
        }
    }
#pragma unroll
    for (int j = 0; j < 2; ++j) {
        int h = hb + hg * 2 + j;
        size_t base = ((size_t)(b * Hh + h) * MD + kx) * CO + 4 * oq;
        *(u64*)&g_Gx[base    ] = re[j][0];
        *(u64*)&g_Gx[base + 2] = re[j][1];
        *(u64*)&g_Gy[base    ] = im[j][0];
        *(u64*)&g_Gy[base + 2] = im[j][1];
    }
}

// ============ stage E: y = S*Gx(0) + sum_{kx>=1} 2S(Gx c - Gy s) ============
#define YPAD 66
__global__ void __launch_bounds__(128) stageE(float* __restrict__ y) {
    __shared__ __align__(16) float sGx[MD * CO];    // 4 KB
    __shared__ __align__(16) float sGy[MD * CO];    // 4 KB
    __shared__ __align__(16) float sY [Ww * YPAD];  // 33.8 KB
    __shared__ __align__(16) u64 sEc[128];
    __shared__ __align__(16) u64 sEs[128];
    int b = blockIdx.x >> 7, h = blockIdx.x & 127;
    int tid = threadIdx.x;                           // = w
    const float SC = 1.0f / 16384.0f;
    {
        float s, c;
        sincosf((float)tid * THETA, &s, &c);
        sEc[tid] = pk(2.0f * SC * c, 2.0f * SC * c);
        sEs[tid] = pk(-2.0f * SC * s, -2.0f * SC * s);
    }
    const float4* Gxs = (const float4*)&g_Gx[(size_t)(b * Hh + h) * MD * CO];
    const float4* Gys = (const float4*)&g_Gy[(size_t)(b * Hh + h) * MD * CO];
    for (int l = tid; l < MD * CO / 4; l += 128) {
        ((float4*)sGx)[l] = Gxs[l];
        ((float4*)sGy)[l] = Gys[l];
    }
    __syncthreads();
    int w = tid;
    u64 tc[16], ts[16];
    tc[0] = pk(SC, SC);  ts[0] = 0;
#pragma unroll
    for (int kx = 1; kx < MD; ++kx) {
        int idx = (kx * w) & 127;
        tc[kx] = sEc[idx];
        ts[kx] = sEs[idx];
    }

#pragma unroll 2
    for (int oq = 0; oq < 16; ++oq) {
        u64 a01 = 0, a23 = 0;
#pragma unroll
        for (int kx = 0; kx < MD; ++kx) {
            ulonglong2 vx = *(const ulonglong2*)&sGx[kx * 64 + oq * 4];
            ulonglong2 vy = *(const ulonglong2*)&sGy[kx * 64 + oq * 4];
            a01 = fma2(vx.x, tc[kx], a01);  a01 = fma2(vy.x, ts[kx], a01);
            a23 = fma2(vx.y, tc[kx], a23);  a23 = fma2(vy.y, ts[kx], a23);
        }
        *(u64*)&sY[w * YPAD + oq * 4    ] = a01;
        *(u64*)&sY[w * YPAD + oq * 4 + 2] = a23;
    }
    __syncthreads();
    float* yb = y + (size_t)(b * Hh + h) * Ww * CO;
    for (int l = tid; l < Ww * CO / 2; l += 128) {
        int idx = l * 2;
        int ww = idx >> 6, o = idx & 63;
        *(u64*)&yb[idx] = *(const u64*)&sY[ww * YPAD + o];
    }
}

extern "C" void kernel_launch(void* const* d_in, const int* in_sizes, int n_in,
                              void* d_out, int out_size) {
    const float* x  = (const float*)d_in[0];
    const float* wr = (const float*)d_in[1];
    const float* wi = (const float*)d_in[2];
    float* y = (float*)d_out;

    fusedAT<<<1536, 128>>>(x, wr, wi);
    stageB<<<B * MD * 2, 256>>>();
    stageC<<<MD * MD, 256>>>();
    stageD<<<B * MD * 4, 256>>>();
    stageE<<<B * Hh, 128>>>(y);
}

// round 9
// speedup vs baseline: 1.1045x; 1.1045x over previous
#include <cuda_runtime.h>
#include <math.h>

#define B   16
#define Hh  128
#define Ww  128
#define CI  64
#define CO  64
#define MD  16
#define THETA 0.04908738521234052f   // 2*pi/128

typedef unsigned long long u64;

__device__ __forceinline__ u64 pk(float lo, float hi) {
    u64 r; asm("mov.b64 %0, {%1,%2};" : "=l"(r) : "f"(lo), "f"(hi)); return r;
}
__device__ __forceinline__ u64 fma2(u64 a, u64 b, u64 c) {
    u64 d; asm("fma.rn.f32x2 %0, %1, %2, %3;" : "=l"(d) : "l"(a), "l"(b), "l"(c)); return d;
}
__device__ __forceinline__ u64 add2(u64 a, u64 b) {
    u64 d; asm("add.rn.f32x2 %0, %1, %2;" : "=l"(d) : "l"(a), "l"(b)); return d;
}
#define SGN2 0x8000000080000000ULL

// ---- scratch (device globals; allocation-free). 16B aligned ----
static __device__ __align__(16) float g_Ax[B*MD*Hh*CI];     // [b][kx][h][i]  8 MB
static __device__ __align__(16) float g_Ay[B*MD*Hh*CI];     //                8 MB
static __device__ __align__(16) float g_Xx[MD*MD*B*CI];     // [m][b][i]      1 MB
static __device__ __align__(16) float g_Xy[MD*MD*B*CI];     //                1 MB
static __device__ __align__(16) float g_Wr[MD*MD*CI*CO];    // [m][i*64+o]    4 MB
static __device__ __align__(16) float g_Wi[MD*MD*CI*CO];    //                4 MB
static __device__ __align__(16) float g_Ox[B*MD*MD*CO];     // [b][kx][ky][o] 1 MB
static __device__ __align__(16) float g_Oy[B*MD*MD*CO];     //                1 MB
static __device__ __align__(16) float g_Gx[B*Hh*MD*CO];     // [b][h][kx][o]  8 MB
static __device__ __align__(16) float g_Gy[B*Hh*MD*CO];     //                8 MB

// ============ fused stage A v3 + weight transpose ============
// blocks [0,1024): A (b, h-quad, i-half).  blocks [1024,2048): transpose tiles.
__global__ void __launch_bounds__(128) fusedAT(const float* __restrict__ x,
                                               const float* __restrict__ wr,
                                               const float* __restrict__ wi) {
    __shared__ __align__(16) float pool[4 * 32 * 32];   // 16 KB
    __shared__ __align__(16) u64 sbc[128];
    __shared__ __align__(16) u64 sbs[128];
    int tid = threadIdx.x;

    if (blockIdx.x >= 1024) {
        // ---- weight transpose tile: 32 m x 32 io ----
        int t   = blockIdx.x - 1024;
        int bm  = t & 7;
        int bio = t >> 3;
        int tx  = tid & 31;
        int ty  = tid >> 5;
        __shared__ float str[2 * 32 * 33];
        #define SR(a_, b_) str[(a_) * 33 + (b_)]
        #define SI(a_, b_) str[1056 + (a_) * 33 + (b_)]
#pragma unroll
        for (int r = 0; r < 8; ++r) {
            int iol = ty + r * 4;
            size_t g = (size_t)(bio * 32 + iol) * 256 + bm * 32 + tx;
            SR(iol, tx) = wr[g];
            SI(iol, tx) = wi[g];
        }
        __syncthreads();
#pragma unroll
        for (int r = 0; r < 8; ++r) {
            int ml = ty + r * 4;
            size_t dst = (size_t)(bm * 32 + ml) * 4096 + bio * 32 + tx;
            g_Wr[dst] = SR(tx, ml);
            g_Wi[dst] = SI(tx, ml);
        }
        return;
    }

    // ---- stage A v3: 4 h rows, 32-i half ----
    {
        float s, c;
        sincosf((float)tid * THETA, &s, &c);
        sbc[tid] = pk(c, c);
        sbs[tid] = pk(s, s);
    }
    int b    = blockIdx.x >> 6;
    int rest = blockIdx.x & 63;
    int hq   = rest >> 1;
    int ic   = rest & 1;
    int h0   = hq * 4;
    int ioff = ic * 32;
    int ip = tid & 15, kq = tid >> 4;      // kx = kq, kq+8
    int i0 = 2 * ip;
    int kxa = kq, kxb = kq + 8;
    u64 re[4][2], im[4][2];
#pragma unroll
    for (int r = 0; r < 4; ++r) { re[r][0]=re[r][1]=im[r][0]=im[r][1]=0; }

    for (int wc = 0; wc < 4; ++wc) {
        __syncthreads();
#pragma unroll
        for (int r = 0; r < 4; ++r) {
            const float4* src = (const float4*)(x + ((size_t)(b * Hh + h0 + r) * Ww + wc * 32) * CI + ioff);
            float4* dst = (float4*)&pool[r * 1024];
            for (int l = tid; l < 256; l += 128) {
                int w = l >> 3, q = l & 7;
                dst[l] = src[w * 16 + q];     // gmem row stride 64 floats = 16 float4
            }
        }
        __syncthreads();
        int w0 = wc * 32;
        int ida = (kxa * w0) & 127;
        int idb = (kxb * w0) & 127;
#pragma unroll 8
        for (int wl = 0; wl < 32; ++wl) {
            u64 v0 = *(const u64*)&pool[0 * 1024 + wl * 32 + i0];
            u64 v1 = *(const u64*)&pool[1 * 1024 + wl * 32 + i0];
            u64 v2 = *(const u64*)&pool[2 * 1024 + wl * 32 + i0];
            u64 v3 = *(const u64*)&pool[3 * 1024 + wl * 32 + i0];
            u64 ca = sbc[ida], sa = sbs[ida];
            u64 cb = sbc[idb], sb = sbs[idb];
            ida = (ida + kxa) & 127;
            idb = (idb + kxb) & 127;
            re[0][0]=fma2(v0,ca,re[0][0]); im[0][0]=fma2(v0,sa,im[0][0]);
            re[1][0]=fma2(v1,ca,re[1][0]); im[1][0]=fma2(v1,sa,im[1][0]);
            re[2][0]=fma2(v2,ca,re[2][0]); im[2][0]=fma2(v2,sa,im[2][0]);
            re[3][0]=fma2(v3,ca,re[3][0]); im[3][0]=fma2(v3,sa,im[3][0]);
            re[0][1]=fma2(v0,cb,re[0][1]); im[0][1]=fma2(v0,sb,im[0][1]);
            re[1][1]=fma2(v1,cb,re[1][1]); im[1][1]=fma2(v1,sb,im[1][1]);
            re[2][1]=fma2(v2,cb,re[2][1]); im[2][1]=fma2(v2,sb,im[2][1]);
            re[3][1]=fma2(v3,cb,re[3][1]); im[3][1]=fma2(v3,sb,im[3][1]);
        }
    }
#pragma unroll
    for (int q = 0; q < 2; ++q) {
        int kx = kq + 8 * q;
#pragma unroll
        for (int r = 0; r < 4; ++r) {
            size_t base = ((size_t)(b * MD + kx) * Hh + (h0 + r)) * CI + ioff;
            *(u64*)&g_Ax[base + i0] = re[r][q];
            *(u64*)&g_Ay[base + i0] = im[r][q] ^ SGN2;   // im = -sum v*s
        }
    }
}

// ============ stage B: X[m][b][i] = sum_h A e^{-i ky h th} ============
__global__ void __launch_bounds__(256) stageB() {
    __shared__ __align__(16) float sBx[64 * 32];
    __shared__ __align__(16) float sBy[64 * 32];
    __shared__ __align__(16) u64 sbc[128];
    __shared__ __align__(16) u64 sbs[128];
    int b  = blockIdx.x >> 5;
    int kx = (blockIdx.x >> 1) & 15;
    int ic = blockIdx.x & 1;
    int tid = threadIdx.x;
    if (tid < 128) {
        float s, c;
        sincosf((float)tid * THETA, &s, &c);
        sbc[tid] = pk(c, c);
        sbs[tid] = pk(s, s);
    }
    int ipl = tid & 15, ky = tid >> 4;
    int i0 = 2 * ipl;
    u64 P = 0, Q = 0, R = 0, S = 0;
    const float* Abx = g_Ax + (size_t)(b * MD + kx) * Hh * CI;
    const float* Aby = g_Ay + (size_t)(b * MD + kx) * Hh * CI;
    for (int hc = 0; hc < 2; ++hc) {
        __syncthreads();
        for (int l = tid; l < 512; l += 256) {
            int row = l >> 3, q = l & 7;
            int gidx = (hc * 64 + row) * 16 + ic * 8 + q;
            ((float4*)sBx)[l] = ((const float4*)Abx)[gidx];
            ((float4*)sBy)[l] = ((const float4*)Aby)[gidx];
        }
        __syncthreads();
        int idx = (ky * hc * 64) & 127;
#pragma unroll 4
        for (int hl = 0; hl < 64; ++hl) {
            u64 cc = sbc[idx], ss = sbs[idx];
            idx = (idx + ky) & 127;
            u64 ar = *(const u64*)&sBx[hl * 32 + i0];
            u64 ai = *(const u64*)&sBy[hl * 32 + i0];
            P = fma2(ar, cc, P);  Q = fma2(ai, ss, Q);
            R = fma2(ai, cc, R);  S = fma2(ar, ss, S);
        }
    }
    size_t base = ((size_t)(ky * MD + kx) * B + b) * CI + ic * 32;
    *(u64*)&g_Xx[base + i0] = add2(P, Q);
    *(u64*)&g_Xy[base + i0] = add2(R, S ^ SGN2);
}

// ============ stage C: O[b][kx][ky][o] = sum_i X[m][b][i]*W[m][i][o] ============
__global__ void __launch_bounds__(256) stageC() {
    __shared__ __align__(16) float sWr[CI * CO];
    __shared__ __align__(16) float sWi[CI * CO];
    __shared__ __align__(16) u64 sXx[B * CI];
    __shared__ __align__(16) u64 sXn[B * CI];
    int m = blockIdx.x;
    int kx = m & 15, ky = m >> 4;
    int tid = threadIdx.x;
    const float4* Wr4 = (const float4*)(g_Wr + (size_t)m * 4096);
    const float4* Wi4 = (const float4*)(g_Wi + (size_t)m * 4096);
    for (int l = tid; l < 1024; l += 256) {
        ((float4*)sWr)[l] = Wr4[l];
        ((float4*)sWi)[l] = Wi4[l];
    }
    for (int l = tid; l < 1024; l += 256) {
        float vx = g_Xx[m * 1024 + l];
        float vy = g_Xy[m * 1024 + l];
        sXx[l] = pk(vx, vx);
        sXn[l] = pk(-vy, -vy);
    }
    __syncthreads();
    int oq = tid & 15;
    int b  = tid >> 4;
    u64 P0=0,P1=0,Q0=0,Q1=0,R0=0,R1=0,S0=0,S1=0;
    const u64* xp = &sXx[b * 64];
    const u64* np = &sXn[b * 64];
#pragma unroll 8
    for (int i = 0; i < CI; ++i) {
        ulonglong2 wr2 = *(const ulonglong2*)&sWr[i * 64 + 4 * oq];
        ulonglong2 wi2 = *(const ulonglong2*)&sWi[i * 64 + 4 * oq];
        u64 xv = xp[i], nv = np[i];
        P0 = fma2(xv, wr2.x, P0);  P1 = fma2(xv, wr2.y, P1);
        Q0 = fma2(nv, wi2.x, Q0);  Q1 = fma2(nv, wi2.y, Q1);
        R0 = fma2(xv, wi2.x, R0);  R1 = fma2(xv, wi2.y, R1);
        S0 = fma2(nv, wr2.x, S0);  S1 = fma2(nv, wr2.y, S1);
    }
    size_t base = ((size_t)(b * MD + kx) * MD + ky) * CO + 4 * oq;
    *(u64*)&g_Ox[base    ] = add2(P0, Q0);
    *(u64*)&g_Ox[base + 2] = add2(P1, Q1);
    *(u64*)&g_Oy[base    ] = add2(R0, S0 ^ SGN2);
    *(u64*)&g_Oy[base + 2] = add2(R1, S1 ^ SGN2);
}

// ============ stage D v3: 512 blocks (b,kx,half), thread = (4 o, 4 h) ============
__global__ void __launch_bounds__(256) stageD() {
    __shared__ __align__(16) float sOx[MD * CO];   // 4 KB
    __shared__ __align__(16) float sOy[MD * CO];   // 4 KB
    __shared__ __align__(16) u64 sTc[MD * 64];     // 8 KB [ky][hloc]
    __shared__ __align__(16) u64 sTs[MD * 64];     // 8 KB
    int half = blockIdx.x & 1;
    int kx   = (blockIdx.x >> 1) & 15;
    int b    = blockIdx.x >> 5;
    int hb   = half * 64;
    int tid  = threadIdx.x;
    for (int l = tid; l < 1024; l += 256) {
        int ky = l >> 6, hloc = l & 63;
        float s, c;
        sincosf((float)((ky * (hb + hloc)) & 127) * THETA, &s, &c);
        sTc[l] = pk(c, c);
        sTs[l] = pk(s, s);
    }
    const float* Osx = g_Ox + (size_t)(b * MD + kx) * MD * CO;
    const float* Osy = g_Oy + (size_t)(b * MD + kx) * MD * CO;
    for (int l = tid; l < 256; l += 256) {
        ((float4*)sOx)[l] = ((const float4*)Osx)[l];
        ((float4*)sOy)[l] = ((const float4*)Osy)[l];
    }
    __syncthreads();

    int oq = tid & 15;    // o = 4*oq (2 pairs)
    int hg = tid >> 4;    // h = hb + 4*hg + j, j 0..3
    u64 re[4][2] = {{0,0},{0,0},{0,0},{0,0}};
    u64 im[4][2] = {{0,0},{0,0},{0,0},{0,0}};
#pragma unroll
    for (int ky = 0; ky < MD; ++ky) {
        ulonglong2 vx = *(const ulonglong2*)&sOx[ky * 64 + 4 * oq];
        ulonglong2 vy = *(const ulonglong2*)&sOy[ky * 64 + 4 * oq];
        u64 vy0n = vy.x ^ SGN2;
        u64 vy1n = vy.y ^ SGN2;
#pragma unroll
        for (int j = 0; j < 4; ++j) {
            int hl = hg * 4 + j;
            u64 cc = sTc[ky * 64 + hl];
            u64 ss = sTs[ky * 64 + hl];
            re[j][0] = fma2(vx.x, cc, re[j][0]);  re[j][0] = fma2(vy0n, ss, re[j][0]);
            re[j][1] = fma2(vx.y, cc, re[j][1]);  re[j][1] = fma2(vy1n, ss, re[j][1]);
            im[j][0] = fma2(vx.x, ss, im[j][0]);  im[j][0] = fma2(vy.x, cc, im[j][0]);
            im[j][1] = fma2(vx.y, ss, im[j][1]);  im[j][1] = fma2(vy.y, cc, im[j][1]);
        }
    }
#pragma unroll
    for (int j = 0; j < 4; ++j) {
        int h = hb + hg * 4 + j;
        size_t base = ((size_t)(b * Hh + h) * MD + kx) * CO + 4 * oq;
        *(u64*)&g_Gx[base    ] = re[j][0];
        *(u64*)&g_Gx[base + 2] = re[j][1];
        *(u64*)&g_Gy[base    ] = im[j][0];
        *(u64*)&g_Gy[base + 2] = im[j][1];
    }
}

// ============ stage E: y = S*Gx(0) + sum_{kx>=1} 2S(Gx c - Gy s) ============
#define YPAD 66
__global__ void __launch_bounds__(128) stageE(float* __restrict__ y) {
    __shared__ __align__(16) float sGx[MD * CO];
    __shared__ __align__(16) float sGy[MD * CO];
    __shared__ __align__(16) float sY [Ww * YPAD];
    __shared__ __align__(16) u64 sEc[128];
    __shared__ __align__(16) u64 sEs[128];
    int b = blockIdx.x >> 7, h = blockIdx.x & 127;
    int tid = threadIdx.x;
    const float SC = 1.0f / 16384.0f;
    {
        float s, c;
        sincosf((float)tid * THETA, &s, &c);
        sEc[tid] = pk(2.0f * SC * c, 2.0f * SC * c);
        sEs[tid] = pk(-2.0f * SC * s, -2.0f * SC * s);
    }
    const float4* Gxs = (const float4*)&g_Gx[(size_t)(b * Hh + h) * MD * CO];
    const float4* Gys = (const float4*)&g_Gy[(size_t)(b * Hh + h) * MD * CO];
    for (int l = tid; l < MD * CO / 4; l += 128) {
        ((float4*)sGx)[l] = Gxs[l];
        ((float4*)sGy)[l] = Gys[l];
    }
    __syncthreads();
    int w = tid;
    u64 tc[16], ts[16];
    tc[0] = pk(SC, SC);  ts[0] = 0;
#pragma unroll
    for (int kx = 1; kx < MD; ++kx) {
        int idx = (kx * w) & 127;
        tc[kx] = sEc[idx];
        ts[kx] = sEs[idx];
    }

#pragma unroll 2
    for (int oq = 0; oq < 16; ++oq) {
        u64 a01 = 0, a23 = 0;
#pragma unroll
        for (int kx = 0; kx < MD; ++kx) {
            ulonglong2 vx = *(const ulonglong2*)&sGx[kx * 64 + oq * 4];
            ulonglong2 vy = *(const ulonglong2*)&sGy[kx * 64 + oq * 4];
            a01 = fma2(vx.x, tc[kx], a01);  a01 = fma2(vy.x, ts[kx], a01);
            a23 = fma2(vx.y, tc[kx], a23);  a23 = fma2(vy.y, ts[kx], a23);
        }
        *(u64*)&sY[w * YPAD + oq * 4    ] = a01;
        *(u64*)&sY[w * YPAD + oq * 4 + 2] = a23;
    }
    __syncthreads();
    float* yb = y + (size_t)(b * Hh + h) * Ww * CO;
    for (int l = tid; l < Ww * CO / 2; l += 128) {
        int idx = l * 2;
        int ww = idx >> 6, o = idx & 63;
        *(u64*)&yb[idx] = *(const u64*)&sY[ww * YPAD + o];
    }
}

extern "C" void kernel_launch(void* const* d_in, const int* in_sizes, int n_in,
                              void* d_out, int out_size) {
    const float* x  = (const float*)d_in[0];
    const float* wr = (const float*)d_in[1];
    const float* wi = (const float*)d_in[2];
    float* y = (float*)d_out;

    fusedAT<<<2048, 128>>>(x, wr, wi);   // 1024 A-blocks + 1024 transpose blocks
    stageB<<<B * MD * 2, 256>>>();
    stageC<<<MD * MD, 256>>>();
    stageD<<<B * MD * 2, 256>>>();
    stageE<<<B * Hh, 128>>>(y);
}

// round 10
// speedup vs baseline: 1.4430x; 1.3064x over previous
#include <cuda_runtime.h>
#include <math.h>

#define B   16
#define Hh  128
#define Ww  128
#define CI  64
#define CO  64
#define MD  16
#define THETA 0.04908738521234052f   // 2*pi/128

typedef unsigned long long u64;

__device__ __forceinline__ u64 pk(float lo, float hi) {
    u64 r; asm("mov.b64 %0, {%1,%2};" : "=l"(r) : "f"(lo), "f"(hi)); return r;
}
__device__ __forceinline__ u64 fma2(u64 a, u64 b, u64 c) {
    u64 d; asm("fma.rn.f32x2 %0, %1, %2, %3;" : "=l"(d) : "l"(a), "l"(b), "l"(c)); return d;
}
__device__ __forceinline__ u64 add2(u64 a, u64 b) {
    u64 d; asm("add.rn.f32x2 %0, %1, %2;" : "=l"(d) : "l"(a), "l"(b)); return d;
}
#define SGN2 0x8000000080000000ULL

// ---- scratch (device globals; allocation-free). 16B aligned ----
static __device__ __align__(16) float g_Ax[B*MD*Hh*CI];     // [b][kx][h][i]
static __device__ __align__(16) float g_Ay[B*MD*Hh*CI];
static __device__ __align__(16) float g_Xx[MD*MD*B*CI];     // [m][b][i]
static __device__ __align__(16) float g_Xy[MD*MD*B*CI];
static __device__ __align__(16) float g_Wr[MD*MD*CI*CO];    // [m][i*64+o]
static __device__ __align__(16) float g_Wi[MD*MD*CI*CO];
static __device__ __align__(16) float g_Ox[B*MD*MD*CO];     // [b][kx][ky][o]
static __device__ __align__(16) float g_Oy[B*MD*MD*CO];
static __device__ __align__(16) float g_Gx[B*Hh*MD*CO];     // [b][h][kx][o]
static __device__ __align__(16) float g_Gy[B*Hh*MD*CO];

// ============ fused stage A (radix-2) + weight transpose ============
// blocks [0,1024): A (b, h-quad, i-half).  blocks [1024,2048): transpose tiles.
__global__ void __launch_bounds__(128) fusedAT(const float* __restrict__ x,
                                               const float* __restrict__ wr,
                                               const float* __restrict__ wi) {
    // pool: per row r (4 rows): up[32*32] then um[32*32]   -> 32 KB
    __shared__ __align__(16) float pool[4 * 2048];
    __shared__ __align__(16) u64 sbc[128];
    __shared__ __align__(16) u64 sbs[128];
    int tid = threadIdx.x;

    if (blockIdx.x >= 1024) {
        // ---- weight transpose tile: 32 m x 32 io ----
        int t   = blockIdx.x - 1024;
        int bm  = t & 7;
        int bio = t >> 3;
        int tx  = tid & 31;
        int ty  = tid >> 5;
        __shared__ float str[2 * 32 * 33];
        #define SR(a_, b_) str[(a_) * 33 + (b_)]
        #define SI(a_, b_) str[1056 + (a_) * 33 + (b_)]
#pragma unroll
        for (int r = 0; r < 8; ++r) {
            int iol = ty + r * 4;
            size_t g = (size_t)(bio * 32 + iol) * 256 + bm * 32 + tx;
            SR(iol, tx) = wr[g];
            SI(iol, tx) = wi[g];
        }
        __syncthreads();
#pragma unroll
        for (int r = 0; r < 8; ++r) {
            int ml = ty + r * 4;
            size_t dst = (size_t)(bm * 32 + ml) * 4096 + bio * 32 + tx;
            g_Wr[dst] = SR(tx, ml);
            g_Wi[dst] = SI(tx, ml);
        }
        return;
    }

    // ---- stage A radix-2: A[kx] = sum_{w<64} (x[w] + (-1)^kx x[w+64]) e^{-i kx w th}
    {
        float s, c;
        sincosf((float)tid * THETA, &s, &c);
        sbc[tid] = pk(c, c);
        sbs[tid] = pk(s, s);
    }
    int b    = blockIdx.x >> 6;
    int rest = blockIdx.x & 63;
    int hq   = rest >> 1;
    int ic   = rest & 1;
    int h0   = hq * 4;
    int ioff = ic * 32;
    int ip = tid & 15, kq = tid >> 4;      // kx = kq, kq+8 (same parity)
    int i0 = 2 * ip;
    int kxa = kq, kxb = kq + 8;
    int du = (kq & 1) * 1024;              // odd kx -> um buffer
    u64 re[4][2], im[4][2];
#pragma unroll
    for (int r = 0; r < 4; ++r) { re[r][0]=re[r][1]=im[r][0]=im[r][1]=0; }

    for (int wc = 0; wc < 2; ++wc) {       // w' chunks of 32 (w' in 0..63)
        __syncthreads();
#pragma unroll
        for (int r = 0; r < 4; ++r) {
            const float4* src = (const float4*)(x + ((size_t)(b * Hh + h0 + r) * Ww + wc * 32) * CI + ioff);
            float4* dp = (float4*)&pool[r * 2048];
            float4* dm = (float4*)&pool[r * 2048 + 1024];
            for (int l = tid; l < 256; l += 128) {
                int w = l >> 3, q = l & 7;
                float4 a = src[w * 16 + q];            // x[w']
                float4 c = src[w * 16 + q + 1024];     // x[w'+64] (+64*16 float4)
                dp[l] = make_float4(a.x + c.x, a.y + c.y, a.z + c.z, a.w + c.w);
                dm[l] = make_float4(a.x - c.x, a.y - c.y, a.z - c.z, a.w - c.w);
            }
        }
        __syncthreads();
        int w0 = wc * 32;
        int ida = (kxa * w0) & 127;
        int idb = (kxb * w0) & 127;
#pragma unroll 8
        for (int wl = 0; wl < 32; ++wl) {
            u64 v0 = *(const u64*)&pool[0 * 2048 + du + wl * 32 + i0];
            u64 v1 = *(const u64*)&pool[1 * 2048 + du + wl * 32 + i0];
            u64 v2 = *(const u64*)&pool[2 * 2048 + du + wl * 32 + i0];
            u64 v3 = *(const u64*)&pool[3 * 2048 + du + wl * 32 + i0];
            u64 ca = sbc[ida], sa = sbs[ida];
            u64 cb = sbc[idb], sb = sbs[idb];
            ida = (ida + kxa) & 127;
            idb = (idb + kxb) & 127;
            re[0][0]=fma2(v0,ca,re[0][0]); im[0][0]=fma2(v0,sa,im[0][0]);
            re[1][0]=fma2(v1,ca,re[1][0]); im[1][0]=fma2(v1,sa,im[1][0]);
            re[2][0]=fma2(v2,ca,re[2][0]); im[2][0]=fma2(v2,sa,im[2][0]);
            re[3][0]=fma2(v3,ca,re[3][0]); im[3][0]=fma2(v3,sa,im[3][0]);
            re[0][1]=fma2(v0,cb,re[0][1]); im[0][1]=fma2(v0,sb,im[0][1]);
            re[1][1]=fma2(v1,cb,re[1][1]); im[1][1]=fma2(v1,sb,im[1][1]);
            re[2][1]=fma2(v2,cb,re[2][1]); im[2][1]=fma2(v2,sb,im[2][1]);
            re[3][1]=fma2(v3,cb,re[3][1]); im[3][1]=fma2(v3,sb,im[3][1]);
        }
    }
#pragma unroll
    for (int q = 0; q < 2; ++q) {
        int kx = kq + 8 * q;
#pragma unroll
        for (int r = 0; r < 4; ++r) {
            size_t base = ((size_t)(b * MD + kx) * Hh + (h0 + r)) * CI + ioff;
            *(u64*)&g_Ax[base + i0] = re[r][q];
            *(u64*)&g_Ay[base + i0] = im[r][q] ^ SGN2;   // im = -sum v*s
        }
    }
}

// ============ stage B (radix-2): X[m][b][i] = sum_h A e^{-i ky h th} ============
__global__ void __launch_bounds__(256) stageB() {
    __shared__ __align__(16) float upx[64 * 32];   // A[h]+A[h+64] (re)
    __shared__ __align__(16) float umx[64 * 32];   // A[h]-A[h+64] (re)
    __shared__ __align__(16) float upy[64 * 32];   // (im)
    __shared__ __align__(16) float umy[64 * 32];
    __shared__ __align__(16) u64 sbc[128];
    __shared__ __align__(16) u64 sbs[128];
    int b  = blockIdx.x >> 5;
    int kx = (blockIdx.x >> 1) & 15;
    int ic = blockIdx.x & 1;
    int tid = threadIdx.x;
    if (tid < 128) {
        float s, c;
        sincosf((float)tid * THETA, &s, &c);
        sbc[tid] = pk(c, c);
        sbs[tid] = pk(s, s);
    }
    const float4* Abx = (const float4*)(g_Ax + (size_t)(b * MD + kx) * Hh * CI);
    const float4* Aby = (const float4*)(g_Ay + (size_t)(b * MD + kx) * Hh * CI);
    for (int l = tid; l < 512; l += 256) {
        int row = l >> 3, q = l & 7;
        int glo = row * 16 + ic * 8 + q;
        int ghi = (row + 64) * 16 + ic * 8 + q;
        float4 ax = Abx[glo], cx = Abx[ghi];
        float4 ay = Aby[glo], cy = Aby[ghi];
        ((float4*)upx)[l] = make_float4(ax.x+cx.x, ax.y+cx.y, ax.z+cx.z, ax.w+cx.w);
        ((float4*)umx)[l] = make_float4(ax.x-cx.x, ax.y-cx.y, ax.z-cx.z, ax.w-cx.w);
        ((float4*)upy)[l] = make_float4(ay.x+cy.x, ay.y+cy.y, ay.z+cy.z, ay.w+cy.w);
        ((float4*)umy)[l] = make_float4(ay.x-cy.x, ay.y-cy.y, ay.z-cy.z, ay.w-cy.w);
    }
    __syncthreads();
    int ipl = tid & 15, ky = tid >> 4;
    int i0 = 2 * ipl;
    const float* bx = (ky & 1) ? umx : upx;
    const float* by = (ky & 1) ? umy : upy;
    u64 P = 0, Q = 0, R = 0, S = 0;
    int idx = 0;
#pragma unroll 8
    for (int hl = 0; hl < 64; ++hl) {
        u64 cc = sbc[idx], ss = sbs[idx];
        idx = (idx + ky) & 127;
        u64 ar = *(const u64*)&bx[hl * 32 + i0];
        u64 ai = *(const u64*)&by[hl * 32 + i0];
        P = fma2(ar, cc, P);  Q = fma2(ai, ss, Q);
        R = fma2(ai, cc, R);  S = fma2(ar, ss, S);
    }
    size_t base = ((size_t)(ky * MD + kx) * B + b) * CI + ic * 32;
    *(u64*)&g_Xx[base + i0] = add2(P, Q);
    *(u64*)&g_Xy[base + i0] = add2(R, S ^ SGN2);
}

// ============ stage C: O[b][kx][ky][o] = sum_i X[m][b][i]*W[m][i][o] ============
__global__ void __launch_bounds__(256) stageC() {
    __shared__ __align__(16) float sWr[CI * CO];
    __shared__ __align__(16) float sWi[CI * CO];
    __shared__ __align__(16) u64 sXx[B * CI];
    __shared__ __align__(16) u64 sXn[B * CI];
    int m = blockIdx.x;
    int kx = m & 15, ky = m >> 4;
    int tid = threadIdx.x;
    const float4* Wr4 = (const float4*)(g_Wr + (size_t)m * 4096);
    const float4* Wi4 = (const float4*)(g_Wi + (size_t)m * 4096);
    for (int l = tid; l < 1024; l += 256) {
        ((float4*)sWr)[l] = Wr4[l];
        ((float4*)sWi)[l] = Wi4[l];
    }
    for (int l = tid; l < 1024; l += 256) {
        float vx = g_Xx[m * 1024 + l];
        float vy = g_Xy[m * 1024 + l];
        sXx[l] = pk(vx, vx);
        sXn[l] = pk(-vy, -vy);
    }
    __syncthreads();
    int oq = tid & 15;
    int b  = tid >> 4;
    u64 P0=0,P1=0,Q0=0,Q1=0,R0=0,R1=0,S0=0,S1=0;
    const u64* xp = &sXx[b * 64];
    const u64* np = &sXn[b * 64];
#pragma unroll 8
    for (int i = 0; i < CI; ++i) {
        ulonglong2 wr2 = *(const ulonglong2*)&sWr[i * 64 + 4 * oq];
        ulonglong2 wi2 = *(const ulonglong2*)&sWi[i * 64 + 4 * oq];
        u64 xv = xp[i], nv = np[i];
        P0 = fma2(xv, wr2.x, P0);  P1 = fma2(xv, wr2.y, P1);
        Q0 = fma2(nv, wi2.x, Q0);  Q1 = fma2(nv, wi2.y, Q1);
        R0 = fma2(xv, wi2.x, R0);  R1 = fma2(xv, wi2.y, R1);
        S0 = fma2(nv, wr2.x, S0);  S1 = fma2(nv, wr2.y, S1);
    }
    size_t base = ((size_t)(b * MD + kx) * MD + ky) * CO + 4 * oq;
    *(u64*)&g_Ox[base    ] = add2(P0, Q0);
    *(u64*)&g_Ox[base + 2] = add2(P1, Q1);
    *(u64*)&g_Oy[base    ] = add2(R0, S0 ^ SGN2);
    *(u64*)&g_Oy[base + 2] = add2(R1, S1 ^ SGN2);
}

// ============ stage D (radix-2): G[h'] = Se+So, G[h'+64] = Se-So ============
// 512 blocks (b, kx, h'-half of 32), thread = (4 o, 2 h')
__global__ void __launch_bounds__(256) stageD() {
    __shared__ __align__(16) float sOx[MD * CO];
    __shared__ __align__(16) float sOy[MD * CO];
    __shared__ __align__(16) u64 sTc[MD * 32];   // [ky][hl] hl<32
    __shared__ __align__(16) u64 sTs[MD * 32];
    int half = blockIdx.x & 1;
    int kx   = (blockIdx.x >> 1) & 15;
    int b    = blockIdx.x >> 5;
    int hb   = half * 32;                        // h' base (h' < 64)
    int tid  = threadIdx.x;
    for (int l = tid; l < 512; l += 256) {
        int ky = l >> 5, hl = l & 31;
        float s, c;
        sincosf((float)((ky * (hb + hl)) & 127) * THETA, &s, &c);
        sTc[l] = pk(c, c);
        sTs[l] = pk(s, s);
    }
    const float* Osx = g_Ox + (size_t)(b * MD + kx) * MD * CO;
    const float* Osy = g_Oy + (size_t)(b * MD + kx) * MD * CO;
    for (int l = tid; l < 256; l += 256) {
        ((float4*)sOx)[l] = ((const float4*)Osx)[l];
        ((float4*)sOy)[l] = ((const float4*)Osy)[l];
    }
    __syncthreads();

    int oq = tid & 15;    // o = 4*oq (2 pairs)
    int hg = tid >> 4;    // h' = hb + 2*hg + j
    u64 reE[2][2]={{0,0},{0,0}}, imE[2][2]={{0,0},{0,0}};
    u64 reO[2][2]={{0,0},{0,0}}, imO[2][2]={{0,0},{0,0}};
#pragma unroll
    for (int ky = 0; ky < MD; ++ky) {
        ulonglong2 vx = *(const ulonglong2*)&sOx[ky * 64 + 4 * oq];
        ulonglong2 vy = *(const ulonglong2*)&sOy[ky * 64 + 4 * oq];
        u64 vy0n = vy.x ^ SGN2;
        u64 vy1n = vy.y ^ SGN2;
#pragma unroll
        for (int j = 0; j < 2; ++j) {
            int hl = hg * 2 + j;
            u64 cc = sTc[ky * 32 + hl];
            u64 ss = sTs[ky * 32 + hl];
            if ((ky & 1) == 0) {
                reE[j][0] = fma2(vx.x, cc, reE[j][0]);  reE[j][0] = fma2(vy0n, ss, reE[j][0]);
                reE[j][1] = fma2(vx.y, cc, reE[j][1]);  reE[j][1] = fma2(vy1n, ss, reE[j][1]);
                imE[j][0] = fma2(vx.x, ss, imE[j][0]);  imE[j][0] = fma2(vy.x, cc, imE[j][0]);
                imE[j][1] = fma2(vx.y, ss, imE[j][1]);  imE[j][1] = fma2(vy.y, cc, imE[j][1]);
            } else {
                reO[j][0] = fma2(vx.x, cc, reO[j][0]);  reO[j][0] = fma2(vy0n, ss, reO[j][0]);
                reO[j][1] = fma2(vx.y, cc, reO[j][1]);  reO[j][1] = fma2(vy1n, ss, reO[j][1]);
                imO[j][0] = fma2(vx.x, ss, imO[j][0]);  imO[j][0] = fma2(vy.x, cc, imO[j][0]);
                imO[j][1] = fma2(vx.y, ss, imO[j][1]);  imO[j][1] = fma2(vy.y, cc, imO[j][1]);
            }
        }
    }
#pragma unroll
    for (int j = 0; j < 2; ++j) {
        int h = hb + hg * 2 + j;
        size_t b0 = ((size_t)(b * Hh + h     ) * MD + kx) * CO + 4 * oq;
        size_t b1 = ((size_t)(b * Hh + h + 64) * MD + kx) * CO + 4 * oq;
        *(u64*)&g_Gx[b0    ] = add2(reE[j][0], reO[j][0]);
        *(u64*)&g_Gx[b0 + 2] = add2(reE[j][1], reO[j][1]);
        *(u64*)&g_Gy[b0    ] = add2(imE[j][0], imO[j][0]);
        *(u64*)&g_Gy[b0 + 2] = add2(imE[j][1], imO[j][1]);
        *(u64*)&g_Gx[b1    ] = add2(reE[j][0], reO[j][0] ^ SGN2);
        *(u64*)&g_Gx[b1 + 2] = add2(reE[j][1], reO[j][1] ^ SGN2);
        *(u64*)&g_Gy[b1    ] = add2(imE[j][0], imO[j][0] ^ SGN2);
        *(u64*)&g_Gy[b1 + 2] = add2(imE[j][1], imO[j][1] ^ SGN2);
    }
}

// ============ stage E (radix-2): y[w'] = Se+So, y[w'+64] = Se-So ============
#define YPAD 66
__global__ void __launch_bounds__(128) stageE(float* __restrict__ y) {
    __shared__ __align__(16) float sGx[MD * CO];
    __shared__ __align__(16) float sGy[MD * CO];
    __shared__ __align__(16) float sY [Ww * YPAD];
    __shared__ __align__(16) u64 sEc[128];
    __shared__ __align__(16) u64 sEs[128];
    int b = blockIdx.x >> 7, h = blockIdx.x & 127;
    int tid = threadIdx.x;
    const float SC = 1.0f / 16384.0f;
    {
        float s, c;
        sincosf((float)tid * THETA, &s, &c);
        sEc[tid] = pk(2.0f * SC * c, 2.0f * SC * c);
        sEs[tid] = pk(-2.0f * SC * s, -2.0f * SC * s);
    }
    const float4* Gxs = (const float4*)&g_Gx[(size_t)(b * Hh + h) * MD * CO];
    const float4* Gys = (const float4*)&g_Gy[(size_t)(b * Hh + h) * MD * CO];
    for (int l = tid; l < MD * CO / 4; l += 128) {
        ((float4*)sGx)[l] = Gxs[l];
        ((float4*)sGy)[l] = Gys[l];
    }
    __syncthreads();
    int wl   = tid & 63;      // w' < 64
    int ohf  = tid >> 6;      // o-half
    u64 tc[16], ts[16];
    tc[0] = pk(SC, SC);  ts[0] = 0;
#pragma unroll
    for (int kx = 1; kx < MD; ++kx) {
        int idx = (kx * wl) & 127;
        tc[kx] = sEc[idx];
        ts[kx] = sEs[idx];
    }

#pragma unroll 2
    for (int oq = 0; oq < 8; ++oq) {
        int oc = (ohf * 8 + oq) * 4;     // o base (4 floats)
        u64 ae01 = 0, ae23 = 0, ao01 = 0, ao23 = 0;
#pragma unroll
        for (int kx = 0; kx < MD; ++kx) {
            ulonglong2 vx = *(const ulonglong2*)&sGx[kx * 64 + oc];
            ulonglong2 vy = *(const ulonglong2*)&sGy[kx * 64 + oc];
            if ((kx & 1) == 0) {
                ae01 = fma2(vx.x, tc[kx], ae01);  ae01 = fma2(vy.x, ts[kx], ae01);
                ae23 = fma2(vx.y, tc[kx], ae23);  ae23 = fma2(vy.y, ts[kx], ae23);
            } else {
                ao01 = fma2(vx.x, tc[kx], ao01);  ao01 = fma2(vy.x, ts[kx], ao01);
                ao23 = fma2(vx.y, tc[kx], ao23);  ao23 = fma2(vy.y, ts[kx], ao23);
            }
        }
        *(u64*)&sY[ wl       * YPAD + oc    ] = add2(ae01, ao01);
        *(u64*)&sY[ wl       * YPAD + oc + 2] = add2(ae23, ao23);
        *(u64*)&sY[(wl + 64) * YPAD + oc    ] = add2(ae01, ao01 ^ SGN2);
        *(u64*)&sY[(wl + 64) * YPAD + oc + 2] = add2(ae23, ao23 ^ SGN2);
    }
    __syncthreads();
    float* yb = y + (size_t)(b * Hh + h) * Ww * CO;
    for (int l = tid; l < Ww * CO / 2; l += 128) {
        int idx = l * 2;
        int ww = idx >> 6, o = idx & 63;
        *(u64*)&yb[idx] = *(const u64*)&sY[ww * YPAD + o];
    }
}

extern "C" void kernel_launch(void* const* d_in, const int* in_sizes, int n_in,
                              void* d_out, int out_size) {
    const float* x  = (const float*)d_in[0];
    const float* wr = (const float*)d_in[1];
    const float* wi = (const float*)d_in[2];
    float* y = (float*)d_out;

    fusedAT<<<2048, 128>>>(x, wr, wi);
    stageB<<<B * MD * 2, 256>>>();
    stageC<<<MD * MD, 256>>>();
    stageD<<<B * MD * 2, 256>>>();
    stageE<<<B * Hh, 128>>>(y);
}

// round 11
// speedup vs baseline: 1.5207x; 1.0539x over previous
#include <cuda_runtime.h>
#include <math.h>

#define B   16
#define Hh  128
#define Ww  128
#define CI  64
#define CO  64
#define MD  16
#define THETA 0.04908738521234052f   // 2*pi/128

typedef unsigned long long u64;

__device__ __forceinline__ u64 pk(float lo, float hi) {
    u64 r; asm("mov.b64 %0, {%1,%2};" : "=l"(r) : "f"(lo), "f"(hi)); return r;
}
__device__ __forceinline__ u64 fma2(u64 a, u64 b, u64 c) {
    u64 d; asm("fma.rn.f32x2 %0, %1, %2, %3;" : "=l"(d) : "l"(a), "l"(b), "l"(c)); return d;
}
__device__ __forceinline__ u64 add2(u64 a, u64 b) {
    u64 d; asm("add.rn.f32x2 %0, %1, %2;" : "=l"(d) : "l"(a), "l"(b)); return d;
}
#define SGN2 0x8000000080000000ULL

// ---- scratch (device globals; allocation-free). 16B aligned ----
static __device__ __align__(16) float g_Ax[B*MD*Hh*CI];     // [b][kx][h][i]
static __device__ __align__(16) float g_Ay[B*MD*Hh*CI];
static __device__ __align__(16) float g_Xx[MD*MD*B*CI];     // [m][b][i]
static __device__ __align__(16) float g_Xy[MD*MD*B*CI];
static __device__ __align__(16) float g_Wr[MD*MD*CI*CO];    // [m][i*64+o]
static __device__ __align__(16) float g_Wi[MD*MD*CI*CO];
static __device__ __align__(16) float g_Ox[B*MD*MD*CO];     // [b][kx][ky][o]
static __device__ __align__(16) float g_Oy[B*MD*MD*CO];
static __device__ __align__(16) float g_Gx[B*Hh*MD*CO];     // [b][h][kx][o]
static __device__ __align__(16) float g_Gy[B*Hh*MD*CO];

// ============ fused stage A v4 (radix-2) + weight transpose ============
// blocks [0,1024): A (b, h-pair). blocks [1024,2048): transpose tiles.
__global__ void __launch_bounds__(256) fusedAT(const float* __restrict__ x,
                                               const float* __restrict__ wr,
                                               const float* __restrict__ wi) {
    // A: pool[row 2][par 2][wl 32][i 64] = 8192 floats (32 KB); T: aliased transpose tiles
    __shared__ __align__(16) float pool[8192];
    __shared__ __align__(16) u64 sbc[128];
    __shared__ __align__(16) u64 sbs[128];
    int tid = threadIdx.x;

    if (blockIdx.x >= 1024) {
        // ---- weight transpose tile: 32 m x 32 io ----
        int t   = blockIdx.x - 1024;
        int bm  = t & 7;
        int bio = t >> 3;
        int tx  = tid & 31;
        int ty  = tid >> 5;                 // 0..7
        float* sr = pool;                   // [32][33]
        float* si = pool + 1056;
#pragma unroll
        for (int r = 0; r < 4; ++r) {
            int iol = ty + r * 8;
            size_t g = (size_t)(bio * 32 + iol) * 256 + bm * 32 + tx;
            sr[iol * 33 + tx] = wr[g];
            si[iol * 33 + tx] = wi[g];
        }
        __syncthreads();
#pragma unroll
        for (int r = 0; r < 4; ++r) {
            int ml = ty + r * 8;
            size_t dst = (size_t)(bm * 32 + ml) * 4096 + bio * 32 + tx;
            g_Wr[dst] = sr[tx * 33 + ml];
            g_Wi[dst] = si[tx * 33 + ml];
        }
        return;
    }

    // ---- stage A: A[kx] = sum_{w'<64} u_{par(kx)}[w'] e^{-i kx w' th} ----
    if (tid < 128) {
        float s, c;
        sincosf((float)tid * THETA, &s, &c);
        sbc[tid] = pk(c, c);
        sbs[tid] = pk(s, s);
    }
    int b  = blockIdx.x >> 6;
    int hp = blockIdx.x & 63;
    int h0 = hp * 2;
    int ipair = tid & 31, kq = tid >> 5;   // kx = kq, kq+8 (same parity); warp-uniform kq
    int i0 = 2 * ipair;
    int kxa = kq, kxb = kq + 8;
    int du = (kq & 1) * 2048;              // odd kx -> um region
    u64 reA0=0, imA0=0, reB0=0, imB0=0;    // row0: kxa, kxb
    u64 reA1=0, imA1=0, reB1=0, imB1=0;    // row1

    for (int wc = 0; wc < 2; ++wc) {
        __syncthreads();
#pragma unroll
        for (int r = 0; r < 2; ++r) {
            const ulonglong2* src = (const ulonglong2*)(x + ((size_t)(b * Hh + h0 + r) * Ww + wc * 32) * CI);
            ulonglong2* dp = (ulonglong2*)&pool[r * 4096];
            ulonglong2* dm = (ulonglong2*)&pool[r * 4096 + 2048];
            for (int l = tid; l < 512; l += 256) {
                ulonglong2 a = src[l];            // x[w']
                ulonglong2 c = src[l + 1024];     // x[w'+64]
                ulonglong2 p, m;
                p.x = add2(a.x, c.x);         p.y = add2(a.y, c.y);
                m.x = add2(a.x, c.x ^ SGN2);  m.y = add2(a.y, c.y ^ SGN2);
                dp[l] = p;
                dm[l] = m;
            }
        }
        __syncthreads();
        int ida = (kxa * (wc * 32)) & 127;
        int idb = (kxb * (wc * 32)) & 127;
#pragma unroll 8
        for (int wl = 0; wl < 32; ++wl) {
            u64 v0 = *(const u64*)&pool[du + wl * 64 + i0];
            u64 v1 = *(const u64*)&pool[4096 + du + wl * 64 + i0];
            u64 ca = sbc[ida], sa = sbs[ida];
            u64 cb = sbc[idb], sb = sbs[idb];
            ida = (ida + kxa) & 127;
            idb = (idb + kxb) & 127;
            reA0 = fma2(v0, ca, reA0);  imA0 = fma2(v0, sa, imA0);
            reA1 = fma2(v1, ca, reA1);  imA1 = fma2(v1, sa, imA1);
            reB0 = fma2(v0, cb, reB0);  imB0 = fma2(v0, sb, imB0);
            reB1 = fma2(v1, cb, reB1);  imB1 = fma2(v1, sb, imB1);
        }
    }
    size_t baseA0 = ((size_t)(b * MD + kxa) * Hh + h0    ) * CI;
    size_t baseA1 = ((size_t)(b * MD + kxa) * Hh + h0 + 1) * CI;
    size_t baseB0 = ((size_t)(b * MD + kxb) * Hh + h0    ) * CI;
    size_t baseB1 = ((size_t)(b * MD + kxb) * Hh + h0 + 1) * CI;
    *(u64*)&g_Ax[baseA0 + i0] = reA0;  *(u64*)&g_Ay[baseA0 + i0] = imA0 ^ SGN2;
    *(u64*)&g_Ax[baseA1 + i0] = reA1;  *(u64*)&g_Ay[baseA1 + i0] = imA1 ^ SGN2;
    *(u64*)&g_Ax[baseB0 + i0] = reB0;  *(u64*)&g_Ay[baseB0 + i0] = imB0 ^ SGN2;
    *(u64*)&g_Ax[baseB1 + i0] = reB1;  *(u64*)&g_Ay[baseB1 + i0] = imB1 ^ SGN2;
}

// ============ stage B v2 (radix-2, full i per block): X[m][b][i] = sum_h A e^{-i ky h th} ============
__global__ void __launch_bounds__(256) stageB() {
    __shared__ __align__(16) float bxp[32 * 64];   // u+ (re) 8 KB
    __shared__ __align__(16) float bxm[32 * 64];   // u- (re)
    __shared__ __align__(16) float byp[32 * 64];   // u+ (im)
    __shared__ __align__(16) float bym[32 * 64];   // u- (im)
    __shared__ __align__(16) u64 sbc[128];
    __shared__ __align__(16) u64 sbs[128];
    int b  = blockIdx.x >> 4;
    int kx = blockIdx.x & 15;
    int tid = threadIdx.x;
    if (tid < 128) {
        float s, c;
        sincosf((float)tid * THETA, &s, &c);
        sbc[tid] = pk(c, c);
        sbs[tid] = pk(s, s);
    }
    int ipair = tid & 31, kyg = tid >> 5;   // ky = kyg, kyg+8 (same parity); warp-uniform
    int i0 = 2 * ipair;
    int ky0 = kyg, ky1 = kyg + 8;
    int par = kyg & 1;
    u64 P0=0,Q0=0,R0=0,S0=0, P1=0,Q1=0,R1=0,S1=0;
    const ulonglong2* Abx = (const ulonglong2*)(g_Ax + (size_t)(b * MD + kx) * Hh * CI);
    const ulonglong2* Aby = (const ulonglong2*)(g_Ay + (size_t)(b * MD + kx) * Hh * CI);

    for (int hc = 0; hc < 2; ++hc) {
        __syncthreads();
        for (int l = tid; l < 512; l += 256) {
            int row = l >> 4, q = l & 15;
            int glo = (hc * 32 + row) * 16 + q;
            int ghi = (hc * 32 + row + 64) * 16 + q;
            ulonglong2 ax = Abx[glo], cx = Abx[ghi];
            ulonglong2 ay = Aby[glo], cy = Aby[ghi];
            ulonglong2 t;
            t.x = add2(ax.x, cx.x);        t.y = add2(ax.y, cx.y);
            ((ulonglong2*)bxp)[l] = t;
            t.x = add2(ax.x, cx.x ^ SGN2); t.y = add2(ax.y, cx.y ^ SGN2);
            ((ulonglong2*)bxm)[l] = t;
            t.x = add2(ay.x, cy.x);        t.y = add2(ay.y, cy.y);
            ((ulonglong2*)byp)[l] = t;
            t.x = add2(ay.x, cy.x ^ SGN2); t.y = add2(ay.y, cy.y ^ SGN2);
            ((ulonglong2*)bym)[l] = t;
        }
        __syncthreads();
        const float* bx = par ? bxm : bxp;
        const float* by = par ? bym : byp;
        int idx0 = (ky0 * (hc * 32)) & 127;
        int idx1 = (ky1 * (hc * 32)) & 127;
#pragma unroll 8
        for (int hl = 0; hl < 32; ++hl) {
            u64 ar = *(const u64*)&bx[hl * 64 + i0];
            u64 ai = *(const u64*)&by[hl * 64 + i0];
            u64 cc0 = sbc[idx0], ss0 = sbs[idx0];
            u64 cc1 = sbc[idx1], ss1 = sbs[idx1];
            idx0 = (idx0 + ky0) & 127;
            idx1 = (idx1 + ky1) & 127;
            P0 = fma2(ar, cc0, P0);  Q0 = fma2(ai, ss0, Q0);
            R0 = fma2(ai, cc0, R0);  S0 = fma2(ar, ss0, S0);
            P1 = fma2(ar, cc1, P1);  Q1 = fma2(ai, ss1, Q1);
            R1 = fma2(ai, cc1, R1);  S1 = fma2(ar, ss1, S1);
        }
    }
    // re = P + Q ; im = R - S
    size_t b0 = ((size_t)(ky0 * MD + kx) * B + b) * CI;
    size_t b1 = ((size_t)(ky1 * MD + kx) * B + b) * CI;
    *(u64*)&g_Xx[b0 + i0] = add2(P0, Q0);
    *(u64*)&g_Xy[b0 + i0] = add2(R0, S0 ^ SGN2);
    *(u64*)&g_Xx[b1 + i0] = add2(P1, Q1);
    *(u64*)&g_Xy[b1 + i0] = add2(R1, S1 ^ SGN2);
}

// ============ stage C: O[b][kx][ky][o] = sum_i X[m][b][i]*W[m][i][o] ============
__global__ void __launch_bounds__(256) stageC() {
    __shared__ __align__(16) float sWr[CI * CO];
    __shared__ __align__(16) float sWi[CI * CO];
    __shared__ __align__(16) u64 sXx[B * CI];
    __shared__ __align__(16) u64 sXn[B * CI];
    int m = blockIdx.x;
    int kx = m & 15, ky = m >> 4;
    int tid = threadIdx.x;
    const float4* Wr4 = (const float4*)(g_Wr + (size_t)m * 4096);
    const float4* Wi4 = (const float4*)(g_Wi + (size_t)m * 4096);
    for (int l = tid; l < 1024; l += 256) {
        ((float4*)sWr)[l] = Wr4[l];
        ((float4*)sWi)[l] = Wi4[l];
    }
    for (int l = tid; l < 1024; l += 256) {
        float vx = g_Xx[m * 1024 + l];
        float vy = g_Xy[m * 1024 + l];
        sXx[l] = pk(vx, vx);
        sXn[l] = pk(-vy, -vy);
    }
    __syncthreads();
    int oq = tid & 15;
    int b  = tid >> 4;
    u64 P0=0,P1=0,Q0=0,Q1=0,R0=0,R1=0,S0=0,S1=0;
    const u64* xp = &sXx[b * 64];
    const u64* np = &sXn[b * 64];
#pragma unroll 8
    for (int i = 0; i < CI; ++i) {
        ulonglong2 wr2 = *(const ulonglong2*)&sWr[i * 64 + 4 * oq];
        ulonglong2 wi2 = *(const ulonglong2*)&sWi[i * 64 + 4 * oq];
        u64 xv = xp[i], nv = np[i];
        P0 = fma2(xv, wr2.x, P0);  P1 = fma2(xv, wr2.y, P1);
        Q0 = fma2(nv, wi2.x, Q0);  Q1 = fma2(nv, wi2.y, Q1);
        R0 = fma2(xv, wi2.x, R0);  R1 = fma2(xv, wi2.y, R1);
        S0 = fma2(nv, wr2.x, S0);  S1 = fma2(nv, wr2.y, S1);
    }
    size_t base = ((size_t)(b * MD + kx) * MD + ky) * CO + 4 * oq;
    *(u64*)&g_Ox[base    ] = add2(P0, Q0);
    *(u64*)&g_Ox[base + 2] = add2(P1, Q1);
    *(u64*)&g_Oy[base    ] = add2(R0, S0 ^ SGN2);
    *(u64*)&g_Oy[base + 2] = add2(R1, S1 ^ SGN2);
}

// ============ stage D (radix-2): G[h'] = Se+So, G[h'+64] = Se-So ============
__global__ void __launch_bounds__(256, 4) stageD() {
    __shared__ __align__(16) float sOx[MD * CO];
    __shared__ __align__(16) float sOy[MD * CO];
    __shared__ __align__(16) u64 sTc[MD * 32];   // [ky][hl] hl<32
    __shared__ __align__(16) u64 sTs[MD * 32];
    int half = blockIdx.x & 1;
    int kx   = (blockIdx.x >> 1) & 15;
    int b    = blockIdx.x >> 5;
    int hb   = half * 32;                        // h' base (h' < 64)
    int tid  = threadIdx.x;
    for (int l = tid; l < 512; l += 256) {
        int ky = l >> 5, hl = l & 31;
        float s, c;
        sincosf((float)((ky * (hb + hl)) & 127) * THETA, &s, &c);
        sTc[l] = pk(c, c);
        sTs[l] = pk(s, s);
    }
    const float* Osx = g_Ox + (size_t)(b * MD + kx) * MD * CO;
    const float* Osy = g_Oy + (size_t)(b * MD + kx) * MD * CO;
    for (int l = tid; l < 256; l += 256) {
        ((float4*)sOx)[l] = ((const float4*)Osx)[l];
        ((float4*)sOy)[l] = ((const float4*)Osy)[l];
    }
    __syncthreads();

    int oq = tid & 15;    // o = 4*oq (2 pairs)
    int hg = tid >> 4;    // h' = hb + 2*hg + j
    u64 reE[2][2]={{0,0},{0,0}}, imE[2][2]={{0,0},{0,0}};
    u64 reO[2][2]={{0,0},{0,0}}, imO[2][2]={{0,0},{0,0}};
#pragma unroll
    for (int ky = 0; ky < MD; ++ky) {
        ulonglong2 vx = *(const ulonglong2*)&sOx[ky * 64 + 4 * oq];
        ulonglong2 vy = *(const ulonglong2*)&sOy[ky * 64 + 4 * oq];
        u64 vy0n = vy.x ^ SGN2;
        u64 vy1n = vy.y ^ SGN2;
#pragma unroll
        for (int j = 0; j < 2; ++j) {
            int hl = hg * 2 + j;
            u64 cc = sTc[ky * 32 + hl];
            u64 ss = sTs[ky * 32 + hl];
            if ((ky & 1) == 0) {
                reE[j][0] = fma2(vx.x, cc, reE[j][0]);  reE[j][0] = fma2(vy0n, ss, reE[j][0]);
                reE[j][1] = fma2(vx.y, cc, reE[j][1]);  reE[j][1] = fma2(vy1n, ss, reE[j][1]);
                imE[j][0] = fma2(vx.x, ss, imE[j][0]);  imE[j][0] = fma2(vy.x, cc, imE[j][0]);
                imE[j][1] = fma2(vx.y, ss, imE[j][1]);  imE[j][1] = fma2(vy.y, cc, imE[j][1]);
            } else {
                reO[j][0] = fma2(vx.x, cc, reO[j][0]);  reO[j][0] = fma2(vy0n, ss, reO[j][0]);
                reO[j][1] = fma2(vx.y, cc, reO[j][1]);  reO[j][1] = fma2(vy1n, ss, reO[j][1]);
                imO[j][0] = fma2(vx.x, ss, imO[j][0]);  imO[j][0] = fma2(vy.x, cc, imO[j][0]);
                imO[j][1] = fma2(vx.y, ss, imO[j][1]);  imO[j][1] = fma2(vy.y, cc, imO[j][1]);
            }
        }
    }
#pragma unroll
    for (int j = 0; j < 2; ++j) {
        int h = hb + hg * 2 + j;
        size_t b0 = ((size_t)(b * Hh + h     ) * MD + kx) * CO + 4 * oq;
        size_t b1 = ((size_t)(b * Hh + h + 64) * MD + kx) * CO + 4 * oq;
        *(u64*)&g_Gx[b0    ] = add2(reE[j][0], reO[j][0]);
        *(u64*)&g_Gx[b0 + 2] = add2(reE[j][1], reO[j][1]);
        *(u64*)&g_Gy[b0    ] = add2(imE[j][0], imO[j][0]);
        *(u64*)&g_Gy[b0 + 2] = add2(imE[j][1], imO[j][1]);
        *(u64*)&g_Gx[b1    ] = add2(reE[j][0], reO[j][0] ^ SGN2);
        *(u64*)&g_Gx[b1 + 2] = add2(reE[j][1], reO[j][1] ^ SGN2);
        *(u64*)&g_Gy[b1    ] = add2(imE[j][0], imO[j][0] ^ SGN2);
        *(u64*)&g_Gy[b1 + 2] = add2(imE[j][1], imO[j][1] ^ SGN2);
    }
}

// ============ stage E (radix-2): y[w'] = Se+So, y[w'+64] = Se-So ============
#define YPAD 66
__global__ void __launch_bounds__(128) stageE(float* __restrict__ y) {
    __shared__ __align__(16) float sGx[MD * CO];
    __shared__ __align__(16) float sGy[MD * CO];
    __shared__ __align__(16) float sY [Ww * YPAD];
    __shared__ __align__(16) u64 sEc[128];
    __shared__ __align__(16) u64 sEs[128];
    int b = blockIdx.x >> 7, h = blockIdx.x & 127;
    int tid = threadIdx.x;
    const float SC = 1.0f / 16384.0f;
    {
        float s, c;
        sincosf((float)tid * THETA, &s, &c);
        sEc[tid] = pk(2.0f * SC * c, 2.0f * SC * c);
        sEs[tid] = pk(-2.0f * SC * s, -2.0f * SC * s);
    }
    const float4* Gxs = (const float4*)&g_Gx[(size_t)(b * Hh + h) * MD * CO];
    const float4* Gys = (const float4*)&g_Gy[(size_t)(b * Hh + h) * MD * CO];
    for (int l = tid; l < MD * CO / 4; l += 128) {
        ((float4*)sGx)[l] = Gxs[l];
        ((float4*)sGy)[l] = Gys[l];
    }
    __syncthreads();
    int wl   = tid & 63;      // w' < 64
    int ohf  = tid >> 6;      // o-half
    u64 tc[16], ts[16];
    tc[0] = pk(SC, SC);  ts[0] = 0;
#pragma unroll
    for (int kx = 1; kx < MD; ++kx) {
        int idx = (kx * wl) & 127;
        tc[kx] = sEc[idx];
        ts[kx] = sEs[idx];
    }

#pragma unroll 2
    for (int oq = 0; oq < 8; ++oq) {
        int oc = (ohf * 8 + oq) * 4;     // o base (4 floats)
        u64 ae01 = 0, ae23 = 0, ao01 = 0, ao23 = 0;
#pragma unroll
        for (int kx = 0; kx < MD; ++kx) {
            ulonglong2 vx = *(const ulonglong2*)&sGx[kx * 64 + oc];
            ulonglong2 vy = *(const ulonglong2*)&sGy[kx * 64 + oc];
            if ((kx & 1) == 0) {
                ae01 = fma2(vx.x, tc[kx], ae01);  ae01 = fma2(vy.x, ts[kx], ae01);
                ae23 = fma2(vx.y, tc[kx], ae23);  ae23 = fma2(vy.y, ts[kx], ae23);
            } else {
                ao01 = fma2(vx.x, tc[kx], ao01);  ao01 = fma2(vy.x, ts[kx], ao01);
                ao23 = fma2(vx.y, tc[kx], ao23);  ao23 = fma2(vy.y, ts[kx], ao23);
            }
        }
        *(u64*)&sY[ wl       * YPAD + oc    ] = add2(ae01, ao01);
        *(u64*)&sY[ wl       * YPAD + oc + 2] = add2(ae23, ao23);
        *(u64*)&sY[(wl + 64) * YPAD + oc    ] = add2(ae01, ao01 ^ SGN2);
        *(u64*)&sY[(wl + 64) * YPAD + oc + 2] = add2(ae23, ao23 ^ SGN2);
    }
    __syncthreads();
    float* yb = y + (size_t)(b * Hh + h) * Ww * CO;
    for (int l = tid; l < Ww * CO / 2; l += 128) {
        int idx = l * 2;
        int ww = idx >> 6, o = idx & 63;
        *(u64*)&yb[idx] = *(const u64*)&sY[ww * YPAD + o];
    }
}

extern "C" void kernel_launch(void* const* d_in, const int* in_sizes, int n_in,
                              void* d_out, int out_size) {
    const float* x  = (const float*)d_in[0];
    const float* wr = (const float*)d_in[1];
    const float* wi = (const float*)d_in[2];
    float* y = (float*)d_out;

    fusedAT<<<2048, 256>>>(x, wr, wi);   // 1024 A-blocks + 1024 transpose blocks
    stageB<<<B * MD, 256>>>();
    stageC<<<MD * MD, 256>>>();
    stageD<<<B * MD * 2, 256>>>();
    stageE<<<B * Hh, 128>>>(y);
}